// round 1
// baseline (speedup 1.0000x reference)
#include <cuda_runtime.h>

#define B_ 8
#define CH_ 16
#define N_ 64
#define MT_ 12
#define MM_ 24
#define NMODE (MM_*MM_*MT_)   /* 6912 */

// Scratch (device globals; allocation-free per harness rules)
__device__ float2 g_A[B_*CH_*N_*N_*MT_];      // 50.3 MB : fwd_t out, reused as inv_y out
__device__ float2 g_B[B_*CH_*N_*MM_*MT_];     // 18.9 MB : fwd_y out, reused as inv_x out
__device__ float2 g_C[B_*CH_*NMODE];          // 7.1 MB  : fwd_x out
__device__ float2 g_D[B_*CH_*NMODE];          // 7.1 MB  : after weight multiply
__device__ float2 g_W[NMODE*CH_*CH_];         // 14.2 MB : transposed weights
__device__ float2 g_tw[64];                   // e^{i 2*pi*j/64} table (cos, sin)

__global__ void tw_init() {
    int j = threadIdx.x;
    float s, c;
    sincospif(j * (1.0f / 32.0f), &s, &c);
    g_tw[j] = make_float2(c, s);
}

// Repack weights: g_W[mode][i*16+o], mode = (my*24+mx)*12+kt, corner-selected
__global__ void wtrans(const float* __restrict__ w1, const float* __restrict__ w2,
                       const float* __restrict__ w3, const float* __restrict__ w4) {
    int m  = blockIdx.x;          // 0..NMODE-1
    int io = threadIdx.x;         // 0..255
    int kt = m % 12;
    int mm = m / 12;
    int mx = mm % 24;
    int my = mm / 24;
    const float* w = (mx < 12) ? ((my < 12) ? w1 : w3) : ((my < 12) ? w2 : w4);
    int wi1 = mx % 12, wi2 = my % 12;
    int i = io >> 4, o = io & 15;
    const float* p = w + (size_t)((((i*16 + o)*12 + wi1)*12 + wi2)*12 + kt) * 2;
    g_W[(size_t)m * 256 + io] = make_float2(p[0], p[1]);
}

// Stage 1: real DFT along t (64 -> 12 modes). block per (b,c,x); 64 threads (one per y)
__global__ void fwd_t(const float* __restrict__ x) {
    __shared__ float xs[64][65];
    __shared__ float twc[64], tws[64];
    int tid = threadIdx.x;
    int bcx = blockIdx.x;
    { float2 t = g_tw[tid]; twc[tid] = t.x; tws[tid] = t.y; }
    const float* xp = x + (size_t)bcx * 4096;
    for (int i = tid; i < 4096; i += 64) xs[i >> 6][i & 63] = xp[i];
    __syncthreads();
    int y = tid;
    float ar[12], ai[12];
    #pragma unroll
    for (int k = 0; k < 12; k++) { ar[k] = 0.f; ai[k] = 0.f; }
    for (int t = 0; t < 64; t++) {
        float s = xs[y][t];
        #pragma unroll
        for (int k = 0; k < 12; k++) {
            int id = (k * t) & 63;
            ar[k] += s * twc[id];
            ai[k] -= s * tws[id];
        }
    }
    float2* out = g_A + ((size_t)bcx * 64 + y) * 12;
    #pragma unroll
    for (int k = 0; k < 12; k++) out[k] = make_float2(ar[k], ai[k]);
}

// Stage 2: complex DFT along y (64 -> 24 modes). block per (b,c,x); 288 threads
__global__ void fwd_y() {
    __shared__ float2 as[768];
    __shared__ float twc[64], tws[64];
    int tid = threadIdx.x;
    if (tid < 64) { float2 t = g_tw[tid]; twc[tid] = t.x; tws[tid] = t.y; }
    const float2* in = g_A + (size_t)blockIdx.x * 768;
    for (int i = tid; i < 768; i += 288) as[i] = in[i];
    __syncthreads();
    int kt = tid % 12, my = tid / 12;
    int ky = (my < 12) ? my : my + 40;
    float ar = 0.f, ai = 0.f;
    #pragma unroll 8
    for (int y = 0; y < 64; y++) {
        float2 a = as[y * 12 + kt];
        int id = (ky * y) & 63;
        float c = twc[id], s = tws[id];
        ar += a.x * c + a.y * s;   // multiply by e^{-i theta}
        ai += a.y * c - a.x * s;
    }
    g_B[(size_t)blockIdx.x * 288 + tid] = make_float2(ar, ai);
}

// Stage 3: complex DFT along x (64 -> 24 modes). block per (b,c,my); 288 threads
__global__ void fwd_x() {
    __shared__ float2 as[768];
    __shared__ float twc[64], tws[64];
    int tid = threadIdx.x;
    if (tid < 64) { float2 t = g_tw[tid]; twc[tid] = t.x; tws[tid] = t.y; }
    int bc = blockIdx.x / 24;
    int my = blockIdx.x % 24;
    for (int i = tid; i < 768; i += 288) {
        int x = i / 12, kt = i % 12;
        as[i] = g_B[((size_t)bc * 64 + x) * 288 + my * 12 + kt];
    }
    __syncthreads();
    int kt = tid % 12, mx = tid / 12;
    int kx = (mx < 12) ? mx : mx + 40;
    float ar = 0.f, ai = 0.f;
    #pragma unroll 8
    for (int x = 0; x < 64; x++) {
        float2 a = as[x * 12 + kt];
        int id = (kx * x) & 63;
        float c = twc[id], s = tws[id];
        ar += a.x * c + a.y * s;
        ai += a.y * c - a.x * s;
    }
    // g_C[b,c, my, mx, kt] : mode = my*288 + mx*12 + kt
    g_C[((size_t)bc * 24 + my) * 288 + tid] = make_float2(ar, ai);
}

// Stage 4: per-mode complex channel mix out[o] = sum_i a[i] * w[i,o]
__global__ void mulw() {
    __shared__ float2 ws[256];
    __shared__ float2 as[128];
    int m = blockIdx.x, tid = threadIdx.x;   // 128 threads
    ws[tid]       = g_W[(size_t)m * 256 + tid];
    ws[tid + 128] = g_W[(size_t)m * 256 + tid + 128];
    int b = tid >> 4, i = tid & 15;
    as[tid] = g_C[(size_t)(b * 16 + i) * NMODE + m];
    __syncthreads();
    int o = tid & 15;
    float ar = 0.f, ai = 0.f;
    #pragma unroll
    for (int ii = 0; ii < 16; ii++) {
        float2 a = as[b * 16 + ii];
        float2 w = ws[ii * 16 + o];
        ar += a.x * w.x - a.y * w.y;
        ai += a.x * w.y + a.y * w.x;
    }
    g_D[(size_t)(b * 16 + o) * NMODE + m] = make_float2(ar, ai);
}

// Stage 5: inverse DFT along x (24 modes -> 64). block per (b,o,my); 256 threads x 3 outputs
__global__ void inv_x() {
    __shared__ float2 as[288];
    __shared__ float twc[64], tws[64];
    int tid = threadIdx.x;
    if (tid < 64) { float2 t = g_tw[tid]; twc[tid] = t.x; tws[tid] = t.y; }
    const float2* in = g_D + (size_t)blockIdx.x * 288;
    for (int i = tid; i < 288; i += 256) as[i] = in[i];
    __syncthreads();
    for (int j = tid; j < 768; j += 256) {
        int x = j / 12, kt = j % 12;
        float ar = 0.f, ai = 0.f;
        #pragma unroll
        for (int mx = 0; mx < 24; mx++) {
            float2 a = as[mx * 12 + kt];
            int kx = (mx < 12) ? mx : mx + 40;
            int id = (kx * x) & 63;
            float c = twc[id], s = tws[id];
            ar += a.x * c - a.y * s;   // multiply by e^{+i theta}
            ai += a.x * s + a.y * c;
        }
        g_B[(size_t)blockIdx.x * 768 + j] = make_float2(ar, ai);  // [b,o,my,x,kt]
    }
}

// Stage 6: inverse DFT along y (24 modes -> 64). block per (b,o,x); 256 threads x 3 outputs
__global__ void inv_y() {
    __shared__ float2 as[288];
    __shared__ float twc[64], tws[64];
    int tid = threadIdx.x;
    if (tid < 64) { float2 t = g_tw[tid]; twc[tid] = t.x; tws[tid] = t.y; }
    int bo = blockIdx.x / 64;
    int x  = blockIdx.x % 64;
    for (int i = tid; i < 288; i += 256) {
        int my = i / 12, kt = i % 12;
        as[i] = g_B[((size_t)(bo * 24 + my)) * 768 + x * 12 + kt];
    }
    __syncthreads();
    for (int j = tid; j < 768; j += 256) {
        int y = j / 12, kt = j % 12;
        float ar = 0.f, ai = 0.f;
        #pragma unroll
        for (int my = 0; my < 24; my++) {
            float2 a = as[my * 12 + kt];
            int ky = (my < 12) ? my : my + 40;
            int id = (ky * y) & 63;
            float c = twc[id], s = tws[id];
            ar += a.x * c - a.y * s;
            ai += a.x * s + a.y * c;
        }
        g_A[(size_t)blockIdx.x * 768 + j] = make_float2(ar, ai);  // [b,o,x,y,kt]
    }
}

// Stage 7 (fused): irfft along t (12 modes -> 64 real) + scale + ReLU + 1x1 channel mix + bias
__global__ void final_k(const float* __restrict__ lo_w, const float* __restrict__ lo_b,
                        float* __restrict__ out) {
    __shared__ float2 fs[16 * 12];
    __shared__ float  ys[16 * 64];
    __shared__ float  lw[256];
    __shared__ float  lb[16];
    __shared__ float  twc[64], tws[64];
    int tid = threadIdx.x;   // 256
    int b  = blockIdx.x >> 12;
    int xy = blockIdx.x & 4095;
    if (tid < 64) { float2 t = g_tw[tid]; twc[tid] = t.x; tws[tid] = t.y; }
    lw[tid] = lo_w[tid];
    if (tid < 16) lb[tid] = lo_b[tid];
    if (tid < 192) {
        int c = tid / 12, kt = tid % 12;
        fs[tid] = g_A[((size_t)(b * 16 + c) * 4096 + xy) * 12 + kt];
    }
    __syncthreads();
    const float SC = 1.0f / 262144.0f;   // 1/(64^3) irfftn normalization
    for (int j = tid; j < 1024; j += 256) {
        int c = j >> 6, t = j & 63;
        float c0 = twc[t], s0 = tws[t];   // e^{+i 2 pi t / 64}
        float cr = c0, ci = s0;
        float acc = fs[c * 12].x;         // k=0: Re only (irfft semantics)
        #pragma unroll
        for (int k = 1; k < 12; k++) {
            float2 f = fs[c * 12 + k];
            acc += 2.0f * (f.x * cr - f.y * ci);
            float nr = cr * c0 - ci * s0;
            ci = cr * s0 + ci * c0;
            cr = nr;
        }
        acc *= SC;
        ys[j] = acc > 0.0f ? acc : 0.0f;  // ReLU
    }
    __syncthreads();
    for (int j = tid; j < 1024; j += 256) {
        int o = j >> 6, t = j & 63;
        float acc = lb[o];
        #pragma unroll
        for (int c = 0; c < 16; c++) acc += lw[o * 16 + c] * ys[c * 64 + t];
        out[((size_t)(b * 16 + o) * 4096 + xy) * 64 + t] = acc;
    }
}

extern "C" void kernel_launch(void* const* d_in, const int* in_sizes, int n_in,
                              void* d_out, int out_size) {
    const float* x    = (const float*)d_in[0];
    const float* w1   = (const float*)d_in[1];
    const float* w2   = (const float*)d_in[2];
    const float* w3   = (const float*)d_in[3];
    const float* w4   = (const float*)d_in[4];
    const float* lo_w = (const float*)d_in[5];
    const float* lo_b = (const float*)d_in[6];
    float* out = (float*)d_out;

    tw_init<<<1, 64>>>();
    wtrans<<<NMODE, 256>>>(w1, w2, w3, w4);
    fwd_t<<<B_ * CH_ * N_, 64>>>(x);
    fwd_y<<<B_ * CH_ * N_, 288>>>();
    fwd_x<<<B_ * CH_ * MM_, 288>>>();
    mulw<<<NMODE, 128>>>();
    inv_x<<<B_ * CH_ * MM_, 256>>>();
    inv_y<<<B_ * CH_ * N_, 256>>>();
    final_k<<<B_ * N_ * N_, 256>>>(lo_w, lo_b, out);
}

// round 3
// speedup vs baseline: 1.1145x; 1.1145x over previous
#include <cuda_runtime.h>

#define B_ 8
#define CH_ 16
#define N_ 64
#define MT_ 12
#define MM_ 24
#define NMODE (MM_*MM_*MT_)   /* 6912 */
#define SC_ (1.0f/262144.0f)  /* 1/64^3 */

// Scratch (device globals; allocation-free per harness rules)
__device__ float2 g_A[B_*CH_*N_*N_*MT_];      // 50.3 MB : fwd_t out [bc][x][y][kt]; reused inv_y out [bo][x][y][kt]
__device__ float2 g_B[B_*CH_*N_*MM_*MT_];     // 18.9 MB : fwd_y out [bc][x][my][kt]; reused inv_x out [bo][my][x][kt]
__device__ float2 g_C[B_*CH_*NMODE];          // 7.1 MB  : fwd_x out [mode][bi]
__device__ float2 g_D[B_*CH_*NMODE];          // 7.1 MB  : mulw out  [bi][mode]

// ---------------- Stage 1: real DFT along t (64 -> 12 modes) ----------------
// block per (b,c,x) slice; 64 threads = (kgroup of 3) x (ygroup of 4)
__global__ __launch_bounds__(64) void fwd_t(const float* __restrict__ x) {
    __shared__ float xs[64 * 65];
    int tid = threadIdx.x;
    const float* xp = x + (size_t)blockIdx.x * 4096;
    for (int i = tid; i < 4096; i += 64) {
        int y = i >> 6, t = i & 63;
        xs[t * 65 + y] = xp[i];          // transposed, pad 65 => conflict-free
    }
    __syncthreads();
    int kg = tid >> 4, yg = tid & 15;
    int y0 = yg * 4;
    float ar[3][4], ai[3][4], wr[3], wi[3], cs[3], sn[3];
    #pragma unroll
    for (int kk = 0; kk < 3; kk++) {
        int k = kg * 3 + kk;
        float s, c; sincospif(k * (1.0f / 32.0f), &s, &c);
        cs[kk] = c; sn[kk] = s; wr[kk] = 1.0f; wi[kk] = 0.0f;
        #pragma unroll
        for (int yy = 0; yy < 4; yy++) { ar[kk][yy] = 0.f; ai[kk][yy] = 0.f; }
    }
    #pragma unroll 2
    for (int t = 0; t < 64; t++) {
        float xv[4];
        #pragma unroll
        for (int yy = 0; yy < 4; yy++) xv[yy] = xs[t * 65 + y0 + yy];
        #pragma unroll
        for (int kk = 0; kk < 3; kk++) {
            #pragma unroll
            for (int yy = 0; yy < 4; yy++) {
                ar[kk][yy] += xv[yy] * wr[kk];
                ai[kk][yy] += xv[yy] * wi[kk];
            }
            float nr = wr[kk] * cs[kk] + wi[kk] * sn[kk];   // w *= e^{-i w0 k}
            wi[kk]   = wi[kk] * cs[kk] - wr[kk] * sn[kk];
            wr[kk]   = nr;
        }
    }
    __syncthreads();
    float2* os = (float2*)xs;            // reuse smem for coalesced writeback
    #pragma unroll
    for (int kk = 0; kk < 3; kk++)
        #pragma unroll
        for (int yy = 0; yy < 4; yy++)
            os[(y0 + yy) * 12 + kg * 3 + kk] = make_float2(ar[kk][yy], ai[kk][yy]);
    __syncthreads();
    float2* outp = g_A + (size_t)blockIdx.x * 768;
    for (int i = tid; i < 768; i += 64) outp[i] = os[i];
}

// ---------------- Stage 2: complex DFT along y (64 -> 24 modes) ----------------
// 8 slices/block, 18 threads/slice = (kyg of 4 modes) x (ktg of 4 kt)
__global__ __launch_bounds__(144) void fwd_y() {
    __shared__ float2 as[8 * 768];
    int tid = threadIdx.x;
    const float2* src = g_A + (size_t)blockIdx.x * 6144;
    for (int i = tid; i < 6144; i += 144) as[i] = src[i];
    __syncthreads();
    int s = tid / 18, r = tid % 18;
    int kyg = r / 3, ktg = r % 3;
    const float2* a = as + s * 768 + ktg * 4;
    float ar[4][4], ai[4][4], wr[4], wi[4], cs[4], sn[4];
    #pragma unroll
    for (int m = 0; m < 4; m++) {
        int my = kyg * 4 + m;
        int ky = (my < 12) ? my : my + 40;
        float ss, cc; sincospif(ky * (1.0f / 32.0f), &ss, &cc);
        cs[m] = cc; sn[m] = ss; wr[m] = 1.0f; wi[m] = 0.0f;
        #pragma unroll
        for (int j = 0; j < 4; j++) { ar[m][j] = 0.f; ai[m][j] = 0.f; }
    }
    #pragma unroll 2
    for (int y = 0; y < 64; y++) {
        float2 av[4];
        #pragma unroll
        for (int j = 0; j < 4; j++) av[j] = a[y * 12 + j];
        #pragma unroll
        for (int m = 0; m < 4; m++) {
            #pragma unroll
            for (int j = 0; j < 4; j++) {
                ar[m][j] += av[j].x * wr[m] - av[j].y * wi[m];
                ai[m][j] += av[j].x * wi[m] + av[j].y * wr[m];
            }
            float nr = wr[m] * cs[m] + wi[m] * sn[m];
            wi[m]    = wi[m] * cs[m] - wr[m] * sn[m];
            wr[m]    = nr;
        }
    }
    int sg = blockIdx.x * 8 + s;          // = bc*64 + x
    float2* outp = g_B + (size_t)sg * 288;
    #pragma unroll
    for (int m = 0; m < 4; m++)
        #pragma unroll
        for (int j = 0; j < 4; j++)
            outp[(kyg * 4 + m) * 12 + ktg * 4 + j] = make_float2(ar[m][j], ai[m][j]);
}

// ---------------- Stage 3: complex DFT along x (64 -> 24 modes) ----------------
// slice = (bc, my); 8 slices/block
__global__ __launch_bounds__(144) void fwd_x() {
    __shared__ float2 as[8 * 768];
    int tid = threadIdx.x;
    int sbase = blockIdx.x * 8;
    for (int i = tid; i < 6144; i += 144) {
        int sl = sbase + i / 768;
        int bc = sl / 24, my = sl % 24;
        int r2 = i % 768;                 // x*12 + kk
        as[i] = g_B[((size_t)(bc * 64 + r2 / 12)) * 288 + my * 12 + (r2 % 12)];
    }
    __syncthreads();
    int s = tid / 18, r = tid % 18;
    int kxg = r / 3, ktg = r % 3;
    const float2* a = as + s * 768 + ktg * 4;
    float ar[4][4], ai[4][4], wr[4], wi[4], cs[4], sn[4];
    #pragma unroll
    for (int m = 0; m < 4; m++) {
        int mx = kxg * 4 + m;
        int kx = (mx < 12) ? mx : mx + 40;
        float ss, cc; sincospif(kx * (1.0f / 32.0f), &ss, &cc);
        cs[m] = cc; sn[m] = ss; wr[m] = 1.0f; wi[m] = 0.0f;
        #pragma unroll
        for (int j = 0; j < 4; j++) { ar[m][j] = 0.f; ai[m][j] = 0.f; }
    }
    #pragma unroll 2
    for (int xx = 0; xx < 64; xx++) {
        float2 av[4];
        #pragma unroll
        for (int j = 0; j < 4; j++) av[j] = a[xx * 12 + j];
        #pragma unroll
        for (int m = 0; m < 4; m++) {
            #pragma unroll
            for (int j = 0; j < 4; j++) {
                ar[m][j] += av[j].x * wr[m] - av[j].y * wi[m];
                ai[m][j] += av[j].x * wi[m] + av[j].y * wr[m];
            }
            float nr = wr[m] * cs[m] + wi[m] * sn[m];
            wi[m]    = wi[m] * cs[m] - wr[m] * sn[m];
            wr[m]    = nr;
        }
    }
    int sl = sbase + s;
    int bc = sl / 24, my = sl % 24;
    #pragma unroll
    for (int m = 0; m < 4; m++)
        #pragma unroll
        for (int j = 0; j < 4; j++) {
            int mode = (my * 24 + (kxg * 4 + m)) * 12 + ktg * 4 + j;
            g_C[(size_t)mode * 128 + bc] = make_float2(ar[m][j], ai[m][j]);
        }
}

// ---------------- Stage 4: per-mode 16x16 complex channel mix ----------------
__global__ __launch_bounds__(128) void mulw(const float* __restrict__ w1, const float* __restrict__ w2,
                                            const float* __restrict__ w3, const float* __restrict__ w4) {
    __shared__ float2 as[128], ws[256];
    int m = blockIdx.x, tid = threadIdx.x;
    as[tid] = g_C[(size_t)m * 128 + tid];
    int kt = m % 12, mm = m / 12, mx = mm % 24, my = mm / 24;
    const float* w = (mx < 12) ? ((my < 12) ? w1 : w3) : ((my < 12) ? w2 : w4);
    int wi1 = mx % 12, wi2 = my % 12;
    for (int io = tid; io < 256; io += 128) {
        const float* p = w + (size_t)(((io * 12 + wi1) * 12 + wi2) * 12 + kt) * 2;
        ws[io] = make_float2(p[0], p[1]);
    }
    __syncthreads();
    int b = tid >> 4, o = tid & 15;
    float ar = 0.f, ai = 0.f;
    #pragma unroll
    for (int i = 0; i < 16; i++) {
        float2 a = as[b * 16 + i];
        float2 wv = ws[i * 16 + o];
        ar += a.x * wv.x - a.y * wv.y;
        ai += a.x * wv.y + a.y * wv.x;
    }
    g_D[(size_t)(b * 16 + o) * NMODE + m] = make_float2(ar, ai);
}

// ---------------- Stage 5: inverse DFT along x (24 modes -> 64) ----------------
// slice = (bo, my); 4 slices/block; 48 thr/slice = (xg of 4 x) x (ktg of 4 kt)
__global__ __launch_bounds__(192) void inv_x() {
    __shared__ float2 as[4 * 288];
    int tid = threadIdx.x;
    int sbase = blockIdx.x * 4;
    for (int i = tid; i < 1152; i += 192) {
        int sl = sbase + i / 288;
        int bo = sl / 24, my = sl % 24;
        as[i] = g_D[(size_t)bo * NMODE + my * 288 + (i % 288)];
    }
    __syncthreads();
    int s = tid / 48, r = tid % 48;
    int xg = r / 3, ktg = r % 3;
    const float2* a = as + s * 288 + ktg * 4;
    float ar[4][4], ai[4][4], pr[4], pi[4], c0[4], s0[4], jr[4], ji[4];
    #pragma unroll
    for (int xi = 0; xi < 4; xi++) {
        int xx = xg * 4 + xi;
        float ss, cc; sincospif(xx * (1.0f / 32.0f), &ss, &cc);
        c0[xi] = cc; s0[xi] = ss;
        sincospif(1.25f * xx, &ss, &cc);   // e^{+i 40 x w0}
        jr[xi] = cc; ji[xi] = ss;
        pr[xi] = 1.0f; pi[xi] = 0.0f;
        #pragma unroll
        for (int j = 0; j < 4; j++) { ar[xi][j] = 0.f; ai[xi][j] = 0.f; }
    }
    #pragma unroll 4
    for (int mx = 0; mx < 24; mx++) {
        if (mx == 12) {
            #pragma unroll
            for (int xi = 0; xi < 4; xi++) {
                float nr = pr[xi] * jr[xi] - pi[xi] * ji[xi];
                pi[xi]   = pr[xi] * ji[xi] + pi[xi] * jr[xi];
                pr[xi]   = nr;
            }
        }
        float2 av[4];
        #pragma unroll
        for (int j = 0; j < 4; j++) av[j] = a[mx * 12 + j];
        #pragma unroll
        for (int xi = 0; xi < 4; xi++) {
            #pragma unroll
            for (int j = 0; j < 4; j++) {
                ar[xi][j] += av[j].x * pr[xi] - av[j].y * pi[xi];
                ai[xi][j] += av[j].x * pi[xi] + av[j].y * pr[xi];
            }
            float nr = pr[xi] * c0[xi] - pi[xi] * s0[xi];   // p *= e^{+i x w0}
            pi[xi]   = pr[xi] * s0[xi] + pi[xi] * c0[xi];
            pr[xi]   = nr;
        }
    }
    int sl = sbase + s;
    int bo = sl / 24, my = sl % 24;
    #pragma unroll
    for (int xi = 0; xi < 4; xi++)
        #pragma unroll
        for (int j = 0; j < 4; j++)
            g_B[((size_t)(bo * 24 + my) * 64 + xg * 4 + xi) * 12 + ktg * 4 + j]
                = make_float2(ar[xi][j], ai[xi][j]);
}

// ---------------- Stage 6: inverse DFT along y (24 modes -> 64) ----------------
// slice = (bo, x); 4 slices/block
__global__ __launch_bounds__(192) void inv_y() {
    __shared__ float2 as[4 * 288];
    int tid = threadIdx.x;
    int sbase = blockIdx.x * 4;
    for (int i = tid; i < 1152; i += 192) {
        int sl = sbase + i / 288;
        int bo = sl / 64, xx = sl % 64;
        int r2 = i % 288;                  // my*12 + kt
        as[i] = g_B[((size_t)(bo * 24 + r2 / 12) * 64 + xx) * 12 + (r2 % 12)];
    }
    __syncthreads();
    int s = tid / 48, r = tid % 48;
    int yg = r / 3, ktg = r % 3;
    const float2* a = as + s * 288 + ktg * 4;
    float ar[4][4], ai[4][4], pr[4], pi[4], c0[4], s0[4], jr[4], ji[4];
    #pragma unroll
    for (int yi = 0; yi < 4; yi++) {
        int yy = yg * 4 + yi;
        float ss, cc; sincospif(yy * (1.0f / 32.0f), &ss, &cc);
        c0[yi] = cc; s0[yi] = ss;
        sincospif(1.25f * yy, &ss, &cc);
        jr[yi] = cc; ji[yi] = ss;
        pr[yi] = 1.0f; pi[yi] = 0.0f;
        #pragma unroll
        for (int j = 0; j < 4; j++) { ar[yi][j] = 0.f; ai[yi][j] = 0.f; }
    }
    #pragma unroll 4
    for (int my = 0; my < 24; my++) {
        if (my == 12) {
            #pragma unroll
            for (int yi = 0; yi < 4; yi++) {
                float nr = pr[yi] * jr[yi] - pi[yi] * ji[yi];
                pi[yi]   = pr[yi] * ji[yi] + pi[yi] * jr[yi];
                pr[yi]   = nr;
            }
        }
        float2 av[4];
        #pragma unroll
        for (int j = 0; j < 4; j++) av[j] = a[my * 12 + j];
        #pragma unroll
        for (int yi = 0; yi < 4; yi++) {
            #pragma unroll
            for (int j = 0; j < 4; j++) {
                ar[yi][j] += av[j].x * pr[yi] - av[j].y * pi[yi];
                ai[yi][j] += av[j].x * pi[yi] + av[j].y * pr[yi];
            }
            float nr = pr[yi] * c0[yi] - pi[yi] * s0[yi];
            pi[yi]   = pr[yi] * s0[yi] + pi[yi] * c0[yi];
            pr[yi]   = nr;
        }
    }
    int sl = sbase + s;                    // = bo*64 + x
    float2* outp = g_A + (size_t)sl * 768;
    #pragma unroll
    for (int yi = 0; yi < 4; yi++)
        #pragma unroll
        for (int j = 0; j < 4; j++)
            outp[(yg * 4 + yi) * 12 + ktg * 4 + j] = make_float2(ar[yi][j], ai[yi][j]);
}

// ---- Stage 7: irfft along t (Horner) + ReLU + 1x1 channel mix + bias ----
__global__ __launch_bounds__(256) void final_k(const float* __restrict__ lo_w,
                                               const float* __restrict__ lo_b,
                                               float* __restrict__ out) {
    __shared__ float2 fsm[192];
    __shared__ float ys[16 * 64];
    __shared__ float lws[256];
    int tid = threadIdx.x;
    int b = blockIdx.x >> 12, xy = blockIdx.x & 4095;
    lws[tid] = lo_w[tid];
    if (tid < 192) {
        int c = tid / 12, k = tid % 12;
        float2 f = g_A[((size_t)(b * 16 + c) * 4096 + xy) * 12 + k];
        float sc = (k == 0) ? SC_ : 2.0f * SC_;
        fsm[tid] = make_float2(f.x * sc, f.y * sc);
    }
    __syncthreads();
    {   // phase 1: complex Horner over 12 t-modes, fs in registers
        int c = tid >> 4, tg = tid & 15;
        float fr[12], fi[12];
        #pragma unroll
        for (int k = 0; k < 12; k++) { float2 f = fsm[c * 12 + k]; fr[k] = f.x; fi[k] = f.y; }
        #pragma unroll
        for (int tt = 0; tt < 4; tt++) {
            int t = tg * 4 + tt;
            float zi, zr; sincospif(t * (1.0f / 32.0f), &zi, &zr);   // z = e^{+i w0 t}
            float sr = fr[11], si = fi[11];
            #pragma unroll
            for (int k = 10; k >= 0; k--) {
                float nr = fr[k] + zr * sr - zi * si;
                si       = fi[k] + zr * si + zi * sr;
                sr       = nr;
            }
            ys[c * 64 + t] = sr > 0.0f ? sr : 0.0f;   // Re(sum) + ReLU
        }
    }
    __syncthreads();
    if (tid < 128) {   // phase 2: 2 outputs x 4 t per thread, lw in registers
        int og = tid >> 4, tg = tid & 15;
        int o0 = og * 2;
        float lwa[16], lwb[16];
        #pragma unroll
        for (int c = 0; c < 16; c++) { lwa[c] = lws[o0 * 16 + c]; lwb[c] = lws[(o0 + 1) * 16 + c]; }
        float b0 = lo_b[o0], b1 = lo_b[o0 + 1];
        float a0[4] = {b0, b0, b0, b0}, a1[4] = {b1, b1, b1, b1};
        #pragma unroll
        for (int c = 0; c < 16; c++) {
            float4 y4 = *(const float4*)&ys[c * 64 + tg * 4];
            a0[0] += lwa[c] * y4.x; a0[1] += lwa[c] * y4.y; a0[2] += lwa[c] * y4.z; a0[3] += lwa[c] * y4.w;
            a1[0] += lwb[c] * y4.x; a1[1] += lwb[c] * y4.y; a1[2] += lwb[c] * y4.z; a1[3] += lwb[c] * y4.w;
        }
        float* p0 = out + ((size_t)(b * 16 + o0) * 4096 + xy) * 64 + tg * 4;
        float* p1 = out + ((size_t)(b * 16 + o0 + 1) * 4096 + xy) * 64 + tg * 4;
        *(float4*)p0 = make_float4(a0[0], a0[1], a0[2], a0[3]);
        *(float4*)p1 = make_float4(a1[0], a1[1], a1[2], a1[3]);
    }
}

extern "C" void kernel_launch(void* const* d_in, const int* in_sizes, int n_in,
                              void* d_out, int out_size) {
    const float* x    = (const float*)d_in[0];
    const float* w1   = (const float*)d_in[1];
    const float* w2   = (const float*)d_in[2];
    const float* w3   = (const float*)d_in[3];
    const float* w4   = (const float*)d_in[4];
    const float* lo_w = (const float*)d_in[5];
    const float* lo_b = (const float*)d_in[6];
    float* out = (float*)d_out;

    fwd_t <<<B_ * CH_ * N_, 64>>>(x);
    fwd_y <<<B_ * CH_ * N_ / 8, 144>>>();
    fwd_x <<<B_ * CH_ * MM_ / 8, 144>>>();
    mulw  <<<NMODE, 128>>>(w1, w2, w3, w4);
    inv_x <<<B_ * CH_ * MM_ / 4, 192>>>();
    inv_y <<<B_ * CH_ * N_ / 4, 192>>>();
    final_k<<<B_ * N_ * N_, 256>>>(lo_w, lo_b, out);
}